// round 1
// baseline (speedup 1.0000x reference)
#include <cuda_runtime.h>
#include <math.h>
#include <float.h>

// Problem constants
#define BN    8
#define TN    4096
#define DN    256
#define INNER 512
#define SN    16
#define BT    32768          // B*T
#define NCODE 240

// ---------------- scratch (static device globals; no allocations) ----------
__device__ float g_xp[(size_t)BT * 1024];   // in_proj output [BT, 2*INNER]
__device__ float g_xc[(size_t)BT * INNER];  // x_conv
__device__ float g_dt[(size_t)BT * INNER];  // dt (softplus applied)
__device__ float g_bc[(size_t)BT * 32];     // [B | C]
__device__ float g_yg[(size_t)BT * INNER];  // scan output, gated

// ---------------- math helpers --------------------------------------------
__device__ __forceinline__ float sigf(float x)  { return 1.f / (1.f + __expf(-x)); }
__device__ __forceinline__ float siluf(float x) { return x * sigf(x); }
__device__ __forceinline__ float softplusf(float x) {
    return x > 20.f ? x : log1pf(__expf(x));
}
__device__ __forceinline__ float geluf(float x) {
    const float c = 0.7978845608028654f;   // sqrt(2/pi)
    float t = tanhf(c * (x + 0.044715f * x * x * x));
    return 0.5f * x * (1.f + t);
}

// ---------------- fp32 SGEMM: 128x128 tile, BK=8, 256 threads, 8x8 micro ---
// C[M,N] = A[M,K] @ B[K,N] + bias[N], optional activation.
// EPI: 0 = none, 1 = silu, 2 = softplus
template <int EPI>
__global__ __launch_bounds__(256)
void sgemm128(const float* __restrict__ A, int lda,
              const float* __restrict__ Bm, int ldb,
              const float* __restrict__ bias,
              float* __restrict__ C, int ldc, int K)
{
    __shared__ float As[8][132];
    __shared__ float Bs[8][132];

    const int tid = threadIdx.x;
    const int bm  = blockIdx.y * 128;
    const int bn  = blockIdx.x * 128;
    const int tm  = (tid >> 4) << 3;      // 0..120
    const int tn  = (tid & 15) << 3;      // 0..120

    const int arow = tid >> 1;            // 0..127
    const int ak   = (tid & 1) << 2;      // 0 or 4
    const int brow = tid >> 5;            // 0..7
    const int bcol = (tid & 31) << 2;     // 0..124

    const float* Aptr = A + (size_t)(bm + arow) * lda + ak;
    const float* Bptr = Bm + (size_t)brow * ldb + bn + bcol;

    float acc[8][8];
#pragma unroll
    for (int i = 0; i < 8; i++)
#pragma unroll
        for (int j = 0; j < 8; j++) acc[i][j] = 0.f;

    for (int kt = 0; kt < K; kt += 8) {
        float4 av = *(const float4*)(Aptr + kt);
        float4 bv = *(const float4*)(Bptr + (size_t)kt * ldb);
        __syncthreads();
        As[ak + 0][arow] = av.x;
        As[ak + 1][arow] = av.y;
        As[ak + 2][arow] = av.z;
        As[ak + 3][arow] = av.w;
        *(float4*)&Bs[brow][bcol] = bv;
        __syncthreads();
#pragma unroll
        for (int kk = 0; kk < 8; kk++) {
            float a[8], b[8];
            *(float4*)(a)     = *(const float4*)&As[kk][tm];
            *(float4*)(a + 4) = *(const float4*)&As[kk][tm + 4];
            *(float4*)(b)     = *(const float4*)&Bs[kk][tn];
            *(float4*)(b + 4) = *(const float4*)&Bs[kk][tn + 4];
#pragma unroll
            for (int i = 0; i < 8; i++)
#pragma unroll
                for (int j = 0; j < 8; j++)
                    acc[i][j] = fmaf(a[i], b[j], acc[i][j]);
        }
    }

#pragma unroll
    for (int i = 0; i < 8; i++) {
        float* crow = C + (size_t)(bm + tm + i) * ldc + bn + tn;
#pragma unroll
        for (int j = 0; j < 8; j++) {
            float v = acc[i][j] + bias[bn + tn + j];
            if (EPI == 1) v = siluf(v);
            else if (EPI == 2) v = softplusf(v);
            crow[j] = v;
        }
    }
}

// ---------------- bc projection: [BT,512] @ [512,32] + b ------------------
__global__ __launch_bounds__(256)
void bc_kernel(const float* __restrict__ xc, const float* __restrict__ w,
               const float* __restrict__ bias, float* __restrict__ out)
{
    __shared__ float srow[8][512];
    const int warp = threadIdx.x >> 5;
    const int lane = threadIdx.x & 31;
    const int r = blockIdx.x * 8 + warp;

    const float* xr = xc + (size_t)r * INNER;
    for (int k = lane; k < INNER; k += 32) srow[warp][k] = xr[k];
    __syncwarp();

    float acc = bias[lane];
#pragma unroll 4
    for (int k = 0; k < INNER; k++)
        acc = fmaf(srow[warp][k], w[k * 32 + lane], acc);
    out[(size_t)r * 32 + lane] = acc;
}

// ---------------- selective scan, S split across 4 lanes -------------------
// thread handles (b, d, q) with q in 0..3 owning s = q*4 .. q*4+3
// lane layout: lane = q*8 + dlow  (dlow = d % 8) -> coalesced dt/xc loads
__global__ __launch_bounds__(128)
void scan_kernel(const float* __restrict__ xc, const float* __restrict__ dt,
                 const float* __restrict__ bc, const float* __restrict__ A_log,
                 const float* __restrict__ xp, float* __restrict__ yg)
{
    const int lane = threadIdx.x & 31;
    const int warp = threadIdx.x >> 5;   // 0..3
    const int dlow = lane & 7;
    const int q    = lane >> 3;          // 0..3
    const int b    = blockIdx.y;
    const int d    = blockIdx.x * 32 + warp * 8 + dlow;

    float A0 = -__expf(A_log[d * SN + q * 4 + 0]);
    float A1 = -__expf(A_log[d * SN + q * 4 + 1]);
    float A2 = -__expf(A_log[d * SN + q * 4 + 2]);
    float A3 = -__expf(A_log[d * SN + q * 4 + 3]);

    float h0 = 0.f, h1 = 0.f, h2 = 0.f, h3 = 0.f;

    const size_t rowbase = (size_t)b * TN;
    const float* dtp = dt + rowbase * INNER + d;
    const float* xcp = xc + rowbase * INNER + d;
    const float* bcp = bc + rowbase * 32;
    const float* gp  = xp + rowbase * 1024 + INNER + d;
    float* yp        = yg + rowbase * INNER + d;

    for (int t = 0; t < TN; t++) {
        const float dtv = dtp[(size_t)t * INNER];
        const float xv  = xcp[(size_t)t * INNER];
        const float4 Bv = *(const float4*)(bcp + (size_t)t * 32 + q * 4);
        const float4 Cv = *(const float4*)(bcp + (size_t)t * 32 + 16 + q * 4);
        const float dtx = dtv * xv;

        h0 = fmaf(__expf(dtv * A0), h0, dtx * Bv.x);
        float ys = h0 * Cv.x;
        h1 = fmaf(__expf(dtv * A1), h1, dtx * Bv.y);
        ys = fmaf(h1, Cv.y, ys);
        h2 = fmaf(__expf(dtv * A2), h2, dtx * Bv.z);
        ys = fmaf(h2, Cv.z, ys);
        h3 = fmaf(__expf(dtv * A3), h3, dtx * Bv.w);
        ys = fmaf(h3, Cv.w, ys);

        ys += __shfl_xor_sync(0xffffffffu, ys, 8);
        ys += __shfl_xor_sync(0xffffffffu, ys, 16);

        if (q == 0) {
            const float g = gp[(size_t)t * 1024];
            yp[(size_t)t * INNER] = ys * siluf(g);
        }
    }
}

// ---------------- catastrophe detector + E8 quantizer ----------------------
// one warp per (b,t) row of y
__global__ __launch_bounds__(256)
void epi_kernel(const float* __restrict__ y,
                const float* __restrict__ cat1_w, const float* __restrict__ cat1_b,
                const float* __restrict__ cat2_w, const float* __restrict__ cat2_b,
                const float* __restrict__ risk_w, const float* __restrict__ risk_b,
                const float* __restrict__ e8a_w,  const float* __restrict__ e8a_b,
                const float* __restrict__ e8b_w,  const float* __restrict__ e8b_b,
                const float* __restrict__ cb,
                float* __restrict__ e8_out, float* __restrict__ idx_out,
                float* __restrict__ bif_out)
{
    __shared__ float sy[8][256];
    __shared__ float sf[8][64];
    __shared__ float se[8][8];

    const int warp = threadIdx.x >> 5;
    const int lane = threadIdx.x & 31;
    const int r = blockIdx.x * 8 + warp;
    const int t = r & (TN - 1);

    const float* yr = y + (size_t)r * DN;
    for (int k = lane; k < DN; k += 32) sy[warp][k] = yr[k];
    __syncwarp();

    // velocity / acceleration norms
    float s1 = 0.f, s2 = 0.f;
    if (t > 0) {
        const float* yp1 = yr - DN;
        for (int k = lane; k < DN; k += 32) {
            float dv = sy[warp][k] - yp1[k];
            s1 = fmaf(dv, dv, s1);
        }
        if (t > 1) {
            const float* yp2 = yr - 2 * DN;
            for (int k = lane; k < DN; k += 32) {
                float dv = yp1[k] - yp2[k];
                s2 = fmaf(dv, dv, s2);
            }
        }
    }
#pragma unroll
    for (int o = 16; o; o >>= 1) {
        s1 += __shfl_xor_sync(0xffffffffu, s1, o);
        s2 += __shfl_xor_sync(0xffffffffu, s2, o);
    }
    const float vn   = sqrtf(s1);
    const float vnp  = sqrtf(s2);
    const float accv = fabsf(vn - vnp);

    // cat1 & e8a hidden layers (64 outs each, 2 per lane)
    float f1a = cat1_b[lane], f1b = cat1_b[lane + 32];
    float e1a = e8a_b[lane],  e1b = e8a_b[lane + 32];
#pragma unroll 4
    for (int k = 0; k < DN; k++) {
        const float yv = sy[warp][k];
        f1a = fmaf(yv, cat1_w[k * 64 + lane], f1a);
        f1b = fmaf(yv, cat1_w[k * 64 + lane + 32], f1b);
        e1a = fmaf(yv, e8a_w[k * 64 + lane], e1a);
        e1b = fmaf(yv, e8a_w[k * 64 + lane + 32], e1b);
    }
    f1a = geluf(f1a); f1b = geluf(f1b);
    e1a = geluf(e1a); e1b = geluf(e1b);

    sf[warp][lane] = f1a; sf[warp][lane + 32] = f1b;
    __syncwarp();

    // cat2 (32 outs) + risk head
    float f2 = cat2_b[lane];
#pragma unroll 8
    for (int k = 0; k < 64; k++)
        f2 = fmaf(sf[warp][k], cat2_w[k * 32 + lane], f2);
    float rp = f2 * risk_w[lane];
#pragma unroll
    for (int o = 16; o; o >>= 1) rp += __shfl_xor_sync(0xffffffffu, rp, o);
    const float risk = sigf(rp + risk_b[0]);

    const float combined = 0.5f * risk + 0.3f * sigf(vn) + 0.2f * sigf(accv);
    if (lane == 0) bif_out[r] = combined > 0.7f ? 1.f : 0.f;

    // e8 code vector (8 outs)
    __syncwarp();
    sf[warp][lane] = e1a; sf[warp][lane + 32] = e1b;
    __syncwarp();
    float e8c = 0.f;
    if (lane < 8) {
        e8c = e8b_b[lane];
#pragma unroll 8
        for (int k = 0; k < 64; k++)
            e8c = fmaf(sf[warp][k], e8b_w[k * 8 + lane], e8c);
        se[warp][lane] = e8c;
    }
    __syncwarp();

    float fn2 = (lane < 8) ? e8c * e8c : 0.f;
#pragma unroll
    for (int o = 16; o; o >>= 1) fn2 += __shfl_xor_sync(0xffffffffu, fn2, o);

    const float f0 = se[warp][0], f1 = se[warp][1], f2v = se[warp][2], f3 = se[warp][3];
    const float f4 = se[warp][4], f5 = se[warp][5], f6v = se[warp][6], f7 = se[warp][7];

    float best = FLT_MAX;
    int bidx = 0x7fffffff;
    for (int c = lane; c < NCODE; c += 32) {
        const float* cp = cb + c * 8;
        float dot = f0 * cp[0] + f1 * cp[1] + f2v * cp[2] + f3 * cp[3]
                  + f4 * cp[4] + f5 * cp[5] + f6v * cp[6] + f7 * cp[7];
        float cn2 = cp[0]*cp[0] + cp[1]*cp[1] + cp[2]*cp[2] + cp[3]*cp[3]
                  + cp[4]*cp[4] + cp[5]*cp[5] + cp[6]*cp[6] + cp[7]*cp[7];
        float d2 = fn2 - 2.f * dot + cn2;
        if (d2 < best) { best = d2; bidx = c; }
    }
#pragma unroll
    for (int o = 16; o; o >>= 1) {
        float ob = __shfl_xor_sync(0xffffffffu, best, o);
        int   oi = __shfl_xor_sync(0xffffffffu, bidx, o);
        if (ob < best || (ob == best && oi < bidx)) { best = ob; bidx = oi; }
    }

    if (lane < 8) {
        const float qv = cb[bidx * 8 + lane];
        const float ec = se[warp][lane];
        e8_out[(size_t)r * 8 + lane] = ec + (qv - ec);   // == q (STE)
    }
    if (lane == 0) idx_out[r] = (float)bidx;
}

// ---------------- launcher --------------------------------------------------
extern "C" void kernel_launch(void* const* d_in, const int* in_sizes, int n_in,
                              void* d_out, int out_size)
{
    const float* x          = (const float*)d_in[0];
    const float* in_proj_w  = (const float*)d_in[1];
    const float* in_proj_b  = (const float*)d_in[2];
    const float* conv_w     = (const float*)d_in[3];
    const float* conv_b     = (const float*)d_in[4];
    const float* A_log      = (const float*)d_in[5];
    const float* bc_w       = (const float*)d_in[6];
    const float* bc_b       = (const float*)d_in[7];
    const float* dt_w       = (const float*)d_in[8];
    const float* dt_b       = (const float*)d_in[9];
    const float* out_w      = (const float*)d_in[10];
    const float* out_b      = (const float*)d_in[11];
    const float* cat1_w     = (const float*)d_in[12];
    const float* cat1_b     = (const float*)d_in[13];
    const float* cat2_w     = (const float*)d_in[14];
    const float* cat2_b     = (const float*)d_in[15];
    const float* risk_w     = (const float*)d_in[16];
    const float* risk_b     = (const float*)d_in[17];
    const float* e8a_w      = (const float*)d_in[18];
    const float* e8a_b      = (const float*)d_in[19];
    const float* e8b_w      = (const float*)d_in[20];
    const float* e8b_b      = (const float*)d_in[21];
    const float* cbk        = (const float*)d_in[22];

    float* out = (float*)d_out;
    float* y_out   = out;                                   // [BT, 256]
    float* e8_out  = out + (size_t)BT * DN;                 // [BT, 8]
    float* idx_out = out + (size_t)BT * DN + (size_t)BT * 8;
    float* bif_out = idx_out + BT;

    float *xp, *xc, *dtb, *bc, *yg;
    cudaGetSymbolAddress((void**)&xp, g_xp);
    cudaGetSymbolAddress((void**)&xc, g_xc);
    cudaGetSymbolAddress((void**)&dtb, g_dt);
    cudaGetSymbolAddress((void**)&bc, g_bc);
    cudaGetSymbolAddress((void**)&yg, g_yg);

    // 1) xp = x @ in_proj_w + b            [BT,1024]
    sgemm128<0><<<dim3(1024 / 128, BT / 128), 256>>>(x, DN, in_proj_w, 1024,
                                                     in_proj_b, xp, 1024, DN);
    // 2) x_conv = silu(x_main @ conv_w + b) [BT,512]  (x_main = xp[:, :512])
    sgemm128<1><<<dim3(INNER / 128, BT / 128), 256>>>(xp, 1024, conv_w, INNER,
                                                      conv_b, xc, INNER, INNER);
    // 3) bc = x_conv @ bc_w + b            [BT,32]
    bc_kernel<<<BT / 8, 256>>>(xc, bc_w, bc_b, bc);
    // 4) dt = softplus(x_conv @ dt_w + b)  [BT,512]
    sgemm128<2><<<dim3(INNER / 128, BT / 128), 256>>>(xc, INNER, dt_w, INNER,
                                                      dt_b, dtb, INNER, INNER);
    // 5) selective scan + gating -> yg     [BT,512]
    scan_kernel<<<dim3(INNER / 32, BN), 128>>>(xc, dtb, bc, A_log, xp, yg);
    // 6) y = yg @ out_w + b -> d_out       [BT,256]
    sgemm128<0><<<dim3(DN / 128, BT / 128), 256>>>(yg, INNER, out_w, DN,
                                                   out_b, y_out, DN, INNER);
    // 7) catastrophe + E8 outputs
    epi_kernel<<<BT / 8, 256>>>(y_out, cat1_w, cat1_b, cat2_w, cat2_b,
                                risk_w, risk_b, e8a_w, e8a_b, e8b_w, e8b_b,
                                cbk, e8_out, idx_out, bif_out);
}

// round 2
// speedup vs baseline: 1.5129x; 1.5129x over previous
#include <cuda_runtime.h>
#include <math.h>
#include <float.h>
#include <stdint.h>

// Problem constants
#define BN    8
#define TN    4096
#define DN    256
#define INNER 512
#define SN    16
#define BT    32768          // B*T
#define NCODE 240

// ---------------- scratch (static device globals; no allocations) ----------
__device__ float g_xp[(size_t)BT * 1024];   // in_proj output [BT, 2*INNER]
__device__ float g_xc[(size_t)BT * INNER];  // x_conv
__device__ float g_dt[(size_t)BT * INNER];  // dt (softplus applied)
__device__ float g_bc[(size_t)BT * 32];     // [B | C]
__device__ float g_yg[(size_t)BT * INNER];  // scan output, gated

// ---------------- math helpers --------------------------------------------
// pure-FMA exp (exp2-based, degree-6 poly): no MUFU, rel err ~1e-7
__device__ __forceinline__ float fexp(float x) {
    float t = x * 1.4426950408889634f;
    t = fminf(fmaxf(t, -100.f), 100.f);
    float z = t + 12582912.0f;                 // round-to-nearest (magic)
    int   n = __float_as_int(z) - 0x4B400000;
    float r = t - (z - 12582912.0f);           // r in [-0.5, 0.5]
    float p = 1.5403530394e-4f;
    p = fmaf(p, r, 1.3333558146e-3f);
    p = fmaf(p, r, 9.6181291076e-3f);
    p = fmaf(p, r, 5.5504108664e-2f);
    p = fmaf(p, r, 2.4022650696e-1f);
    p = fmaf(p, r, 6.9314718056e-1f);
    p = fmaf(p, r, 1.0f);
    return __int_as_float(__float_as_int(p) + (n << 23));
}
// pure-FMA reciprocal (bit trick + 3 Newton steps), x > 0
__device__ __forceinline__ float frcp_fast(float x) {
    float r = __uint_as_float(0x7EF311C3u - __float_as_uint(x));
    r = r * (2.f - x * r);
    r = r * (2.f - x * r);
    r = r * (2.f - x * r);
    return r;
}
__device__ __forceinline__ float fsig(float x)  { return frcp_fast(1.f + fexp(-x)); }
__device__ __forceinline__ float fsilu(float x) { return x * fsig(x); }

__device__ __forceinline__ float sigf(float x)  { return 1.f / (1.f + __expf(-x)); }
__device__ __forceinline__ float softplusf(float x) {
    return x > 20.f ? x : __logf(1.f + fexp(x));
}
__device__ __forceinline__ float geluf(float x) {
    const float c = 0.7978845608028654f;   // sqrt(2/pi)
    float t = tanhf(c * (x + 0.044715f * x * x * x));
    return 0.5f * x * (1.f + t);
}

// ---------------- cp.async helpers -----------------------------------------
__device__ __forceinline__ void cp_async16(void* s, const void* g) {
    uint32_t sa = (uint32_t)__cvta_generic_to_shared(s);
    asm volatile("cp.async.ca.shared.global [%0], [%1], 16;\n" :: "r"(sa), "l"(g));
}
__device__ __forceinline__ void cp_commit() { asm volatile("cp.async.commit_group;\n"); }
__device__ __forceinline__ void cp_wait0()  { asm volatile("cp.async.wait_group 0;\n"); }

// ---------------- fp32 SGEMM: 128x128 tile, BK=8, 256 threads, 8x8 micro ---
// C[M,N] = A[M,K] @ B[K,N] + bias[N], optional activation.
// EPI: 0 = none, 1 = silu, 2 = softplus
// Pipelined: B tile via cp.async double buffer, A tile via register prefetch.
template <int EPI>
__global__ __launch_bounds__(256)
void sgemm128(const float* __restrict__ A, int lda,
              const float* __restrict__ Bm, int ldb,
              const float* __restrict__ bias,
              float* __restrict__ C, int ldc, int K)
{
    __shared__ float As[2][8][132];
    __shared__ float Bs[2][8][132];

    const int tid = threadIdx.x;
    const int bm  = blockIdx.y * 128;
    const int bn  = blockIdx.x * 128;
    const int tm  = (tid >> 4) << 3;      // 0..120
    const int tn  = (tid & 15) << 3;      // 0..120

    const int arow = tid >> 1;            // 0..127
    const int ak   = (tid & 1) << 2;      // 0 or 4
    const int brow = tid >> 5;            // 0..7
    const int bcol = (tid & 31) << 2;     // 0..124

    const float* Aptr = A + (size_t)(bm + arow) * lda + ak;
    const float* Bsrc = Bm + (size_t)brow * ldb + bn + bcol;

    float acc[8][8];
#pragma unroll
    for (int i = 0; i < 8; i++)
#pragma unroll
        for (int j = 0; j < 8; j++) acc[i][j] = 0.f;

    // prologue: tile 0
    float4 av = *(const float4*)(Aptr);
    cp_async16(&Bs[0][brow][bcol], Bsrc);
    cp_commit();

    int stage = 0;
    for (int kt = 0; kt < K; kt += 8, stage ^= 1) {
        As[stage][ak + 0][arow] = av.x;
        As[stage][ak + 1][arow] = av.y;
        As[stage][ak + 2][arow] = av.z;
        As[stage][ak + 3][arow] = av.w;
        cp_wait0();
        __syncthreads();

        if (kt + 8 < K) {
            av = *(const float4*)(Aptr + kt + 8);
            cp_async16(&Bs[stage ^ 1][brow][bcol], Bsrc + (size_t)(kt + 8) * ldb);
            cp_commit();
        }

#pragma unroll
        for (int kk = 0; kk < 8; kk++) {
            float a[8], b[8];
            *(float4*)(a)     = *(const float4*)&As[stage][kk][tm];
            *(float4*)(a + 4) = *(const float4*)&As[stage][kk][tm + 4];
            *(float4*)(b)     = *(const float4*)&Bs[stage][kk][tn];
            *(float4*)(b + 4) = *(const float4*)&Bs[stage][kk][tn + 4];
#pragma unroll
            for (int i = 0; i < 8; i++)
#pragma unroll
                for (int j = 0; j < 8; j++)
                    acc[i][j] = fmaf(a[i], b[j], acc[i][j]);
        }
        __syncthreads();
    }

#pragma unroll
    for (int i = 0; i < 8; i++) {
        float* crow = C + (size_t)(bm + tm + i) * ldc + bn + tn;
#pragma unroll
        for (int j = 0; j < 8; j++) {
            float v = acc[i][j] + bias[bn + tn + j];
            if (EPI == 1) v = fsilu(v);
            else if (EPI == 2) v = softplusf(v);
            crow[j] = v;
        }
    }
}

// ---------------- bc projection: [BT,512] @ [512,32] + b ------------------
__global__ __launch_bounds__(256)
void bc_kernel(const float* __restrict__ xc, const float* __restrict__ w,
               const float* __restrict__ bias, float* __restrict__ out)
{
    __shared__ float srow[8][512];
    const int warp = threadIdx.x >> 5;
    const int lane = threadIdx.x & 31;
    const int r = blockIdx.x * 8 + warp;

    const float* xr = xc + (size_t)r * INNER;
    for (int k = lane; k < INNER; k += 32) srow[warp][k] = xr[k];
    __syncwarp();

    float acc = bias[lane];
#pragma unroll 4
    for (int k = 0; k < INNER; k++)
        acc = fmaf(srow[warp][k], w[k * 32 + lane], acc);
    out[(size_t)r * 32 + lane] = acc;
}

// ---------------- selective scan: one thread per (b, d, s) -----------------
// warp = 2 d-channels x 16 states. lane = half*16 + s.
// 2048 warps total (3.5/SMSP); t+1 operands software-prefetched.
__global__ __launch_bounds__(256)
void scan_kernel(const float* __restrict__ xc, const float* __restrict__ dt,
                 const float* __restrict__ bc, const float* __restrict__ A_log,
                 const float* __restrict__ xp, float* __restrict__ yg)
{
    const int lane = threadIdx.x & 31;
    const int warp = threadIdx.x >> 5;   // 0..7
    const int s    = lane & 15;
    const int half = lane >> 4;          // 0 or 1
    const int b    = blockIdx.y;
    const int d    = blockIdx.x * 16 + warp * 2 + half;

    const float As = -__expf(A_log[d * SN + s]);

    const size_t rowbase = (size_t)b * TN;
    const float* dtp = dt + rowbase * INNER + d;
    const float* xcp = xc + rowbase * INNER + d;
    const float* bcp = bc + rowbase * 32;
    const float* gp  = xp + rowbase * 1024 + INNER + d;
    float* yp        = yg + rowbase * INNER + d;

    float h = 0.f;
    // prologue loads (t = 0)
    float dtv = dtp[0];
    float xv  = xcp[0];
    float Bv  = bcp[s];
    float Cv  = bcp[16 + s];
    float g   = gp[0];

    for (int t = 0; t < TN; t++) {
        float dtn = 0.f, xn = 0.f, Bn = 0.f, Cn = 0.f, gn = 0.f;
        if (t + 1 < TN) {
            const size_t o = (size_t)(t + 1);
            dtn = dtp[o * INNER];
            xn  = xcp[o * INNER];
            Bn  = bcp[o * 32 + s];
            Cn  = bcp[o * 32 + 16 + s];
            gn  = gp[o * 1024];
        }

        const float e = __expf(dtv * As);          // MUFU (idle pipe here)
        h = fmaf(e, h, dtv * xv * Bv);
        float ys = h * Cv;
        ys += __shfl_xor_sync(0xffffffffu, ys, 1);
        ys += __shfl_xor_sync(0xffffffffu, ys, 2);
        ys += __shfl_xor_sync(0xffffffffu, ys, 4);
        ys += __shfl_xor_sync(0xffffffffu, ys, 8);

        const float sv = fsilu(g);                 // pure FMA (keep MUFU free)
        if (s == 0)
            yp[(size_t)t * INNER] = ys * sv;

        dtv = dtn; xv = xn; Bv = Bn; Cv = Cn; g = gn;
    }
}

// ---------------- catastrophe detector + E8 quantizer ----------------------
// one warp per (b,t) row of y
__global__ __launch_bounds__(256)
void epi_kernel(const float* __restrict__ y,
                const float* __restrict__ cat1_w, const float* __restrict__ cat1_b,
                const float* __restrict__ cat2_w, const float* __restrict__ cat2_b,
                const float* __restrict__ risk_w, const float* __restrict__ risk_b,
                const float* __restrict__ e8a_w,  const float* __restrict__ e8a_b,
                const float* __restrict__ e8b_w,  const float* __restrict__ e8b_b,
                const float* __restrict__ cb,
                float* __restrict__ e8_out, float* __restrict__ idx_out,
                float* __restrict__ bif_out)
{
    __shared__ float sy[8][256];
    __shared__ float sf[8][64];
    __shared__ float se[8][8];

    const int warp = threadIdx.x >> 5;
    const int lane = threadIdx.x & 31;
    const int r = blockIdx.x * 8 + warp;
    const int t = r & (TN - 1);

    const float* yr = y + (size_t)r * DN;
    for (int k = lane; k < DN; k += 32) sy[warp][k] = yr[k];
    __syncwarp();

    // velocity / acceleration norms
    float s1 = 0.f, s2 = 0.f;
    if (t > 0) {
        const float* yp1 = yr - DN;
        for (int k = lane; k < DN; k += 32) {
            float dv = sy[warp][k] - yp1[k];
            s1 = fmaf(dv, dv, s1);
        }
        if (t > 1) {
            const float* yp2 = yr - 2 * DN;
            for (int k = lane; k < DN; k += 32) {
                float dv = yp1[k] - yp2[k];
                s2 = fmaf(dv, dv, s2);
            }
        }
    }
#pragma unroll
    for (int o = 16; o; o >>= 1) {
        s1 += __shfl_xor_sync(0xffffffffu, s1, o);
        s2 += __shfl_xor_sync(0xffffffffu, s2, o);
    }
    const float vn   = sqrtf(s1);
    const float vnp  = sqrtf(s2);
    const float accv = fabsf(vn - vnp);

    // cat1 & e8a hidden layers (64 outs each, 2 per lane)
    float f1a = cat1_b[lane], f1b = cat1_b[lane + 32];
    float e1a = e8a_b[lane],  e1b = e8a_b[lane + 32];
#pragma unroll 4
    for (int k = 0; k < DN; k++) {
        const float yv = sy[warp][k];
        f1a = fmaf(yv, cat1_w[k * 64 + lane], f1a);
        f1b = fmaf(yv, cat1_w[k * 64 + lane + 32], f1b);
        e1a = fmaf(yv, e8a_w[k * 64 + lane], e1a);
        e1b = fmaf(yv, e8a_w[k * 64 + lane + 32], e1b);
    }
    f1a = geluf(f1a); f1b = geluf(f1b);
    e1a = geluf(e1a); e1b = geluf(e1b);

    sf[warp][lane] = f1a; sf[warp][lane + 32] = f1b;
    __syncwarp();

    // cat2 (32 outs) + risk head
    float f2 = cat2_b[lane];
#pragma unroll 8
    for (int k = 0; k < 64; k++)
        f2 = fmaf(sf[warp][k], cat2_w[k * 32 + lane], f2);
    float rp = f2 * risk_w[lane];
#pragma unroll
    for (int o = 16; o; o >>= 1) rp += __shfl_xor_sync(0xffffffffu, rp, o);
    const float risk = sigf(rp + risk_b[0]);

    const float combined = 0.5f * risk + 0.3f * sigf(vn) + 0.2f * sigf(accv);
    if (lane == 0) bif_out[r] = combined > 0.7f ? 1.f : 0.f;

    // e8 code vector (8 outs)
    __syncwarp();
    sf[warp][lane] = e1a; sf[warp][lane + 32] = e1b;
    __syncwarp();
    float e8c = 0.f;
    if (lane < 8) {
        e8c = e8b_b[lane];
#pragma unroll 8
        for (int k = 0; k < 64; k++)
            e8c = fmaf(sf[warp][k], e8b_w[k * 8 + lane], e8c);
        se[warp][lane] = e8c;
    }
    __syncwarp();

    float fn2 = (lane < 8) ? e8c * e8c : 0.f;
#pragma unroll
    for (int o = 16; o; o >>= 1) fn2 += __shfl_xor_sync(0xffffffffu, fn2, o);

    const float f0 = se[warp][0], f1 = se[warp][1], f2v = se[warp][2], f3 = se[warp][3];
    const float f4 = se[warp][4], f5 = se[warp][5], f6v = se[warp][6], f7 = se[warp][7];

    float best = FLT_MAX;
    int bidx = 0x7fffffff;
    for (int c = lane; c < NCODE; c += 32) {
        const float* cp = cb + c * 8;
        float dot = f0 * cp[0] + f1 * cp[1] + f2v * cp[2] + f3 * cp[3]
                  + f4 * cp[4] + f5 * cp[5] + f6v * cp[6] + f7 * cp[7];
        float cn2 = cp[0]*cp[0] + cp[1]*cp[1] + cp[2]*cp[2] + cp[3]*cp[3]
                  + cp[4]*cp[4] + cp[5]*cp[5] + cp[6]*cp[6] + cp[7]*cp[7];
        float d2 = fn2 - 2.f * dot + cn2;
        if (d2 < best) { best = d2; bidx = c; }
    }
#pragma unroll
    for (int o = 16; o; o >>= 1) {
        float ob = __shfl_xor_sync(0xffffffffu, best, o);
        int   oi = __shfl_xor_sync(0xffffffffu, bidx, o);
        if (ob < best || (ob == best && oi < bidx)) { best = ob; bidx = oi; }
    }

    if (lane < 8) {
        const float qv = cb[bidx * 8 + lane];
        const float ec = se[warp][lane];
        e8_out[(size_t)r * 8 + lane] = ec + (qv - ec);   // == q (STE)
    }
    if (lane == 0) idx_out[r] = (float)bidx;
}

// ---------------- launcher --------------------------------------------------
extern "C" void kernel_launch(void* const* d_in, const int* in_sizes, int n_in,
                              void* d_out, int out_size)
{
    const float* x          = (const float*)d_in[0];
    const float* in_proj_w  = (const float*)d_in[1];
    const float* in_proj_b  = (const float*)d_in[2];
    const float* conv_w     = (const float*)d_in[3];
    const float* conv_b     = (const float*)d_in[4];
    const float* A_log      = (const float*)d_in[5];
    const float* bc_w       = (const float*)d_in[6];
    const float* bc_b       = (const float*)d_in[7];
    const float* dt_w       = (const float*)d_in[8];
    const float* dt_b       = (const float*)d_in[9];
    const float* out_w      = (const float*)d_in[10];
    const float* out_b      = (const float*)d_in[11];
    const float* cat1_w     = (const float*)d_in[12];
    const float* cat1_b     = (const float*)d_in[13];
    const float* cat2_w     = (const float*)d_in[14];
    const float* cat2_b     = (const float*)d_in[15];
    const float* risk_w     = (const float*)d_in[16];
    const float* risk_b     = (const float*)d_in[17];
    const float* e8a_w      = (const float*)d_in[18];
    const float* e8a_b      = (const float*)d_in[19];
    const float* e8b_w      = (const float*)d_in[20];
    const float* e8b_b      = (const float*)d_in[21];
    const float* cbk        = (const float*)d_in[22];

    float* out = (float*)d_out;
    float* y_out   = out;                                   // [BT, 256]
    float* e8_out  = out + (size_t)BT * DN;                 // [BT, 8]
    float* idx_out = out + (size_t)BT * DN + (size_t)BT * 8;
    float* bif_out = idx_out + BT;

    float *xp, *xc, *dtb, *bc, *yg;
    cudaGetSymbolAddress((void**)&xp, g_xp);
    cudaGetSymbolAddress((void**)&xc, g_xc);
    cudaGetSymbolAddress((void**)&dtb, g_dt);
    cudaGetSymbolAddress((void**)&bc, g_bc);
    cudaGetSymbolAddress((void**)&yg, g_yg);

    // 1) xp = x @ in_proj_w + b            [BT,1024]
    sgemm128<0><<<dim3(1024 / 128, BT / 128), 256>>>(x, DN, in_proj_w, 1024,
                                                     in_proj_b, xp, 1024, DN);
    // 2) x_conv = silu(x_main @ conv_w + b) [BT,512]  (x_main = xp[:, :512])
    sgemm128<1><<<dim3(INNER / 128, BT / 128), 256>>>(xp, 1024, conv_w, INNER,
                                                      conv_b, xc, INNER, INNER);
    // 3) bc = x_conv @ bc_w + b            [BT,32]
    bc_kernel<<<BT / 8, 256>>>(xc, bc_w, bc_b, bc);
    // 4) dt = softplus(x_conv @ dt_w + b)  [BT,512]
    sgemm128<2><<<dim3(INNER / 128, BT / 128), 256>>>(xc, INNER, dt_w, INNER,
                                                      dt_b, dtb, INNER, INNER);
    // 5) selective scan + gating -> yg     [BT,512]
    scan_kernel<<<dim3(INNER / 16, BN), 256>>>(xc, dtb, bc, A_log, xp, yg);
    // 6) y = yg @ out_w + b -> d_out       [BT,256]
    sgemm128<0><<<dim3(DN / 128, BT / 128), 256>>>(yg, INNER, out_w, DN,
                                                   out_b, y_out, DN, INNER);
    // 7) catastrophe + E8 outputs
    epi_kernel<<<BT / 8, 256>>>(y_out, cat1_w, cat1_b, cat2_w, cat2_b,
                                risk_w, risk_b, e8a_w, e8a_b, e8b_w, e8b_b,
                                cbk, e8_out, idx_out, bif_out);
}

// round 3
// speedup vs baseline: 2.5061x; 1.6565x over previous
#include <cuda_runtime.h>
#include <math.h>
#include <float.h>
#include <stdint.h>

// Problem constants
#define BN    8
#define TN    4096
#define DN    256
#define INNER 512
#define SN    16
#define BT    32768          // B*T
#define NCODE 240

// ---------------- scratch (static device globals; no allocations) ----------
__device__ float g_xmain[(size_t)BT * INNER];  // in_proj cols 0..511
__device__ float g_gT[(size_t)INNER * BT];     // silu(gate), transposed [d][bt]
__device__ float g_xc [(size_t)BT * INNER];    // x_conv (normal)
__device__ float g_xcT[(size_t)INNER * BT];    // x_conv transposed
__device__ float g_dtT[(size_t)INNER * BT];    // dt (softplus), transposed
__device__ float g_bcT[(size_t)32 * BT];       // [B|C] transposed [j][bt]
__device__ float g_ygT[(size_t)INNER * BT];    // scan output (gated), transposed

// ---------------- math helpers --------------------------------------------
__device__ __forceinline__ float fexp(float x) {
    float t = x * 1.4426950408889634f;
    t = fminf(fmaxf(t, -100.f), 100.f);
    float z = t + 12582912.0f;
    int   n = __float_as_int(z) - 0x4B400000;
    float r = t - (z - 12582912.0f);
    float p = 1.5403530394e-4f;
    p = fmaf(p, r, 1.3333558146e-3f);
    p = fmaf(p, r, 9.6181291076e-3f);
    p = fmaf(p, r, 5.5504108664e-2f);
    p = fmaf(p, r, 2.4022650696e-1f);
    p = fmaf(p, r, 6.9314718056e-1f);
    p = fmaf(p, r, 1.0f);
    return __int_as_float(__float_as_int(p) + (n << 23));
}
__device__ __forceinline__ float frcp_fast(float x) {
    float r = __uint_as_float(0x7EF311C3u - __float_as_uint(x));
    r = r * (2.f - x * r);
    r = r * (2.f - x * r);
    r = r * (2.f - x * r);
    return r;
}
__device__ __forceinline__ float fsig(float x)  { return frcp_fast(1.f + fexp(-x)); }
__device__ __forceinline__ float fsilu(float x) { return x * fsig(x); }
__device__ __forceinline__ float sigf(float x)  { return 1.f / (1.f + __expf(-x)); }
__device__ __forceinline__ float softplusf(float x) {
    return x > 20.f ? x : __logf(1.f + fexp(x));
}
__device__ __forceinline__ float geluf(float x) {
    const float c = 0.7978845608028654f;
    float t = tanhf(c * (x + 0.044715f * x * x * x));
    return 0.5f * x * (1.f + t);
}

// ---------------- fp32 SGEMM: 128x128 tile, BK=16, 256 threads, 8x8 micro --
// MODE 0: normal store to C (EPI applied)
// MODE 1: transposed store to Ct (EPI applied)   Ct[col][row], row-dim = M
// MODE 2: both stores (EPI applied to both)
// MODE 3: in_proj split: col<512 -> C raw (ldc=512); col>=512 -> Ct silu, row=col-512
// AT: A is stored transposed [K][M] (coalesced loads, like B)
template <int EPI, int MODE, bool AT>
__global__ __launch_bounds__(256)
void sgemm(const float* __restrict__ A, int lda,
           const float* __restrict__ Bm, int ldb,
           const float* __restrict__ bias,
           float* __restrict__ C, int ldc,
           float* __restrict__ Ct, int K)
{
    __shared__ float As[16][132];
    __shared__ float Bs[16][132];

    const int tid = threadIdx.x;
    const int bm  = blockIdx.y * 128;
    const int bn  = blockIdx.x * 128;
    const int M   = gridDim.y * 128;
    const int tm  = (tid >> 4) << 3;
    const int tn  = (tid & 15) << 3;

    // B-style loader indices (also used for A when AT)
    const int brow = tid >> 4;            // 0..15
    const int bcol = (tid & 15) << 3;     // 0..120
    // A loader indices (non-AT)
    const int arow = tid >> 1;            // 0..127
    const int ak   = (tid & 1) << 3;      // 0 or 8

    const float* Bsrc = Bm + (size_t)brow * ldb + bn + bcol;

    float acc[8][8];
#pragma unroll
    for (int i = 0; i < 8; i++)
#pragma unroll
        for (int j = 0; j < 8; j++) acc[i][j] = 0.f;

    float4 a0, a1, b0, b1;
    // prologue loads (tile 0)
    if (AT) {
        const float* Asrc = A + (size_t)brow * M + bm + bcol;
        a0 = *(const float4*)(Asrc);
        a1 = *(const float4*)(Asrc + 4);
    } else {
        const float* Asrc = A + (size_t)(bm + arow) * lda + ak;
        a0 = *(const float4*)(Asrc);
        a1 = *(const float4*)(Asrc + 4);
    }
    b0 = *(const float4*)(Bsrc);
    b1 = *(const float4*)(Bsrc + 4);

    for (int kt = 0; kt < K; kt += 16) {
        __syncthreads();
        if (AT) {
            *(float4*)&As[brow][bcol]     = a0;
            *(float4*)&As[brow][bcol + 4] = a1;
        } else {
            As[ak + 0][arow] = a0.x; As[ak + 1][arow] = a0.y;
            As[ak + 2][arow] = a0.z; As[ak + 3][arow] = a0.w;
            As[ak + 4][arow] = a1.x; As[ak + 5][arow] = a1.y;
            As[ak + 6][arow] = a1.z; As[ak + 7][arow] = a1.w;
        }
        *(float4*)&Bs[brow][bcol]     = b0;
        *(float4*)&Bs[brow][bcol + 4] = b1;
        __syncthreads();

        if (kt + 16 < K) {
            if (AT) {
                const float* Asrc = A + (size_t)(kt + 16 + brow) * M + bm + bcol;
                a0 = *(const float4*)(Asrc);
                a1 = *(const float4*)(Asrc + 4);
            } else {
                const float* Asrc = A + (size_t)(bm + arow) * lda + kt + 16 + ak;
                a0 = *(const float4*)(Asrc);
                a1 = *(const float4*)(Asrc + 4);
            }
            b0 = *(const float4*)(Bsrc + (size_t)(kt + 16) * ldb);
            b1 = *(const float4*)(Bsrc + (size_t)(kt + 16) * ldb + 4);
        }

#pragma unroll
        for (int kk = 0; kk < 16; kk++) {
            float a[8], b[8];
            *(float4*)(a)     = *(const float4*)&As[kk][tm];
            *(float4*)(a + 4) = *(const float4*)&As[kk][tm + 4];
            *(float4*)(b)     = *(const float4*)&Bs[kk][tn];
            *(float4*)(b + 4) = *(const float4*)&Bs[kk][tn + 4];
#pragma unroll
            for (int i = 0; i < 8; i++)
#pragma unroll
                for (int j = 0; j < 8; j++)
                    acc[i][j] = fmaf(a[i], b[j], acc[i][j]);
        }
    }

    // epilogue
    float v[8][8];
#pragma unroll
    for (int i = 0; i < 8; i++)
#pragma unroll
        for (int j = 0; j < 8; j++) {
            float t = acc[i][j] + bias[bn + tn + j];
            if (MODE != 3) {
                if (EPI == 1) t = fsilu(t);
                else if (EPI == 2) t = softplusf(t);
            }
            v[i][j] = t;
        }

    if (MODE == 0 || MODE == 2 || (MODE == 3 && bn < 512)) {
#pragma unroll
        for (int i = 0; i < 8; i++) {
            float* crow = C + (size_t)(bm + tm + i) * ldc + (bn + tn);
            *(float4*)(crow)     = make_float4(v[i][0], v[i][1], v[i][2], v[i][3]);
            *(float4*)(crow + 4) = make_float4(v[i][4], v[i][5], v[i][6], v[i][7]);
        }
    }
    if (MODE == 1 || MODE == 2 || (MODE == 3 && bn >= 512)) {
        const int coff = (MODE == 3) ? (bn - 512) : bn;
#pragma unroll
        for (int j = 0; j < 8; j++) {
            float w0 = v[0][j], w1 = v[1][j], w2 = v[2][j], w3 = v[3][j];
            float w4 = v[4][j], w5 = v[5][j], w6 = v[6][j], w7 = v[7][j];
            if (MODE == 3) {
                w0 = fsilu(w0); w1 = fsilu(w1); w2 = fsilu(w2); w3 = fsilu(w3);
                w4 = fsilu(w4); w5 = fsilu(w5); w6 = fsilu(w6); w7 = fsilu(w7);
            }
            float* ccol = Ct + (size_t)(coff + tn + j) * M + bm + tm;
            *(float4*)(ccol)     = make_float4(w0, w1, w2, w3);
            *(float4*)(ccol + 4) = make_float4(w4, w5, w6, w7);
        }
    }
}

// ---------------- bc projection: [BT,512] @ [512,32] -> bcT [32][BT] ------
__global__ __launch_bounds__(256)
void bc_kernel(const float* __restrict__ xc, const float* __restrict__ w,
               const float* __restrict__ bias, float* __restrict__ bcT)
{
    __shared__ float srow[8][512];
    __shared__ float sbc[8][33];
    const int warp = threadIdx.x >> 5;
    const int lane = threadIdx.x & 31;
    const int r0 = blockIdx.x * 8;
    const int r = r0 + warp;

    const float* xr = xc + (size_t)r * INNER;
    for (int k = lane; k < INNER; k += 32) srow[warp][k] = xr[k];
    __syncwarp();

    float acc = bias[lane];
#pragma unroll 4
    for (int k = 0; k < INNER; k++)
        acc = fmaf(srow[warp][k], w[k * 32 + lane], acc);
    sbc[warp][lane] = acc;
    __syncthreads();

    const int j  = threadIdx.x >> 3;   // 0..31
    const int rr = threadIdx.x & 7;    // 0..7
    bcT[(size_t)j * BT + r0 + rr] = sbc[rr][j];
}

// ---------------- selective scan v3: one thread per (b,d,s), x4 unroll ----
// warp = 2 d x 16 s (lane = half*16 + s). All operands transposed/contiguous.
__global__ __launch_bounds__(256)
void scan_kernel(const float* __restrict__ xcT, const float* __restrict__ dtT,
                 const float* __restrict__ bcT, const float* __restrict__ A_log,
                 const float* __restrict__ gT, float* __restrict__ ygT)
{
    const int lane = threadIdx.x & 31;
    const int warp = threadIdx.x >> 5;   // 0..7
    const int s    = lane & 15;
    const int half = lane >> 4;
    const int b    = blockIdx.y;
    const int d    = blockIdx.x * 16 + warp * 2 + half;

    const float As = -__expf(A_log[d * SN + s]);

    const size_t dbase = (size_t)d * BT + (size_t)b * TN;
    const float4* dt4p = (const float4*)(dtT + dbase);
    const float4* xc4p = (const float4*)(xcT + dbase);
    const float4* g4p  = (const float4*)(gT  + dbase);
    const float4* B4p  = (const float4*)(bcT + (size_t)s * BT + (size_t)b * TN);
    const float4* C4p  = (const float4*)(bcT + (size_t)(16 + s) * BT + (size_t)b * TN);
    float4* y4p        = (float4*)(ygT + dbase);

    float h = 0.f;
    float4 dt4 = dt4p[0], xc4 = xc4p[0], g4 = g4p[0], B4 = B4p[0], C4 = C4p[0];

    const int NG = TN / 4;
    for (int i = 0; i < NG; i++) {
        float4 dtn = dt4, xcn = xc4, gn = g4, Bn = B4, Cn = C4;
        if (i + 1 < NG) {
            dtn = dt4p[i + 1]; xcn = xc4p[i + 1]; gn = g4p[i + 1];
            Bn  = B4p[i + 1];  Cn  = C4p[i + 1];
        }

        // 4 sequential h-updates (short dependent chain), then 4 reductions
        float e0 = __expf(dt4.x * As);
        float e1 = __expf(dt4.y * As);
        float e2 = __expf(dt4.z * As);
        float e3 = __expf(dt4.w * As);

        h = fmaf(e0, h, dt4.x * xc4.x * B4.x); float y0 = h * C4.x;
        h = fmaf(e1, h, dt4.y * xc4.y * B4.y); float y1 = h * C4.y;
        h = fmaf(e2, h, dt4.z * xc4.z * B4.z); float y2 = h * C4.z;
        h = fmaf(e3, h, dt4.w * xc4.w * B4.w); float y3 = h * C4.w;

#pragma unroll
        for (int o = 1; o <= 8; o <<= 1) {
            y0 += __shfl_xor_sync(0xffffffffu, y0, o);
            y1 += __shfl_xor_sync(0xffffffffu, y1, o);
            y2 += __shfl_xor_sync(0xffffffffu, y2, o);
            y3 += __shfl_xor_sync(0xffffffffu, y3, o);
        }

        if (s == 0)   // lanes 0 and 16 (one per d-half); gT already silu'd
            y4p[i] = make_float4(y0 * g4.x, y1 * g4.y, y2 * g4.z, y3 * g4.w);

        dt4 = dtn; xc4 = xcn; g4 = gn; B4 = Bn; C4 = Cn;
    }
}

// ---------------- catastrophe detector + E8 quantizer ----------------------
__global__ __launch_bounds__(256)
void epi_kernel(const float* __restrict__ y,
                const float* __restrict__ cat1_w, const float* __restrict__ cat1_b,
                const float* __restrict__ cat2_w, const float* __restrict__ cat2_b,
                const float* __restrict__ risk_w, const float* __restrict__ risk_b,
                const float* __restrict__ e8a_w,  const float* __restrict__ e8a_b,
                const float* __restrict__ e8b_w,  const float* __restrict__ e8b_b,
                const float* __restrict__ cb,
                float* __restrict__ e8_out, float* __restrict__ idx_out,
                float* __restrict__ bif_out)
{
    __shared__ float sy[8][256];
    __shared__ float sf[8][64];
    __shared__ float se[8][8];

    const int warp = threadIdx.x >> 5;
    const int lane = threadIdx.x & 31;
    const int r = blockIdx.x * 8 + warp;
    const int t = r & (TN - 1);

    const float* yr = y + (size_t)r * DN;
    for (int k = lane; k < DN; k += 32) sy[warp][k] = yr[k];
    __syncwarp();

    float s1 = 0.f, s2 = 0.f;
    if (t > 0) {
        const float* yp1 = yr - DN;
        for (int k = lane; k < DN; k += 32) {
            float dv = sy[warp][k] - yp1[k];
            s1 = fmaf(dv, dv, s1);
        }
        if (t > 1) {
            const float* yp2 = yr - 2 * DN;
            for (int k = lane; k < DN; k += 32) {
                float dv = yp1[k] - yp2[k];
                s2 = fmaf(dv, dv, s2);
            }
        }
    }
#pragma unroll
    for (int o = 16; o; o >>= 1) {
        s1 += __shfl_xor_sync(0xffffffffu, s1, o);
        s2 += __shfl_xor_sync(0xffffffffu, s2, o);
    }
    const float vn   = sqrtf(s1);
    const float vnp  = sqrtf(s2);
    const float accv = fabsf(vn - vnp);

    float f1a = cat1_b[lane], f1b = cat1_b[lane + 32];
    float e1a = e8a_b[lane],  e1b = e8a_b[lane + 32];
#pragma unroll 4
    for (int k = 0; k < DN; k++) {
        const float yv = sy[warp][k];
        f1a = fmaf(yv, cat1_w[k * 64 + lane], f1a);
        f1b = fmaf(yv, cat1_w[k * 64 + lane + 32], f1b);
        e1a = fmaf(yv, e8a_w[k * 64 + lane], e1a);
        e1b = fmaf(yv, e8a_w[k * 64 + lane + 32], e1b);
    }
    f1a = geluf(f1a); f1b = geluf(f1b);
    e1a = geluf(e1a); e1b = geluf(e1b);

    sf[warp][lane] = f1a; sf[warp][lane + 32] = f1b;
    __syncwarp();

    float f2 = cat2_b[lane];
#pragma unroll 8
    for (int k = 0; k < 64; k++)
        f2 = fmaf(sf[warp][k], cat2_w[k * 32 + lane], f2);
    float rp = f2 * risk_w[lane];
#pragma unroll
    for (int o = 16; o; o >>= 1) rp += __shfl_xor_sync(0xffffffffu, rp, o);
    const float risk = sigf(rp + risk_b[0]);

    const float combined = 0.5f * risk + 0.3f * sigf(vn) + 0.2f * sigf(accv);
    if (lane == 0) bif_out[r] = combined > 0.7f ? 1.f : 0.f;

    __syncwarp();
    sf[warp][lane] = e1a; sf[warp][lane + 32] = e1b;
    __syncwarp();
    float e8c = 0.f;
    if (lane < 8) {
        e8c = e8b_b[lane];
#pragma unroll 8
        for (int k = 0; k < 64; k++)
            e8c = fmaf(sf[warp][k], e8b_w[k * 8 + lane], e8c);
        se[warp][lane] = e8c;
    }
    __syncwarp();

    float fn2 = (lane < 8) ? e8c * e8c : 0.f;
#pragma unroll
    for (int o = 16; o; o >>= 1) fn2 += __shfl_xor_sync(0xffffffffu, fn2, o);

    const float f0 = se[warp][0], f1 = se[warp][1], f2v = se[warp][2], f3 = se[warp][3];
    const float f4 = se[warp][4], f5 = se[warp][5], f6v = se[warp][6], f7 = se[warp][7];

    float best = FLT_MAX;
    int bidx = 0x7fffffff;
    for (int c = lane; c < NCODE; c += 32) {
        const float* cp = cb + c * 8;
        float dot = f0 * cp[0] + f1 * cp[1] + f2v * cp[2] + f3 * cp[3]
                  + f4 * cp[4] + f5 * cp[5] + f6v * cp[6] + f7 * cp[7];
        float cn2 = cp[0]*cp[0] + cp[1]*cp[1] + cp[2]*cp[2] + cp[3]*cp[3]
                  + cp[4]*cp[4] + cp[5]*cp[5] + cp[6]*cp[6] + cp[7]*cp[7];
        float d2 = fn2 - 2.f * dot + cn2;
        if (d2 < best) { best = d2; bidx = c; }
    }
#pragma unroll
    for (int o = 16; o; o >>= 1) {
        float ob = __shfl_xor_sync(0xffffffffu, best, o);
        int   oi = __shfl_xor_sync(0xffffffffu, bidx, o);
        if (ob < best || (ob == best && oi < bidx)) { best = ob; bidx = oi; }
    }

    if (lane < 8) {
        const float qv = cb[bidx * 8 + lane];
        const float ec = se[warp][lane];
        e8_out[(size_t)r * 8 + lane] = ec + (qv - ec);
    }
    if (lane == 0) idx_out[r] = (float)bidx;
}

// ---------------- launcher --------------------------------------------------
extern "C" void kernel_launch(void* const* d_in, const int* in_sizes, int n_in,
                              void* d_out, int out_size)
{
    const float* x          = (const float*)d_in[0];
    const float* in_proj_w  = (const float*)d_in[1];
    const float* in_proj_b  = (const float*)d_in[2];
    const float* conv_w     = (const float*)d_in[3];
    const float* conv_b     = (const float*)d_in[4];
    const float* A_log      = (const float*)d_in[5];
    const float* bc_w       = (const float*)d_in[6];
    const float* bc_b       = (const float*)d_in[7];
    const float* dt_w       = (const float*)d_in[8];
    const float* dt_b       = (const float*)d_in[9];
    const float* out_w      = (const float*)d_in[10];
    const float* out_b      = (const float*)d_in[11];
    const float* cat1_w     = (const float*)d_in[12];
    const float* cat1_b     = (const float*)d_in[13];
    const float* cat2_w     = (const float*)d_in[14];
    const float* cat2_b     = (const float*)d_in[15];
    const float* risk_w     = (const float*)d_in[16];
    const float* risk_b     = (const float*)d_in[17];
    const float* e8a_w      = (const float*)d_in[18];
    const float* e8a_b      = (const float*)d_in[19];
    const float* e8b_w      = (const float*)d_in[20];
    const float* e8b_b      = (const float*)d_in[21];
    const float* cbk        = (const float*)d_in[22];

    float* out = (float*)d_out;
    float* y_out   = out;
    float* e8_out  = out + (size_t)BT * DN;
    float* idx_out = out + (size_t)BT * DN + (size_t)BT * 8;
    float* bif_out = idx_out + BT;

    float *xmain, *gT, *xc, *xcT, *dtT, *bcT, *ygT;
    cudaGetSymbolAddress((void**)&xmain, g_xmain);
    cudaGetSymbolAddress((void**)&gT, g_gT);
    cudaGetSymbolAddress((void**)&xc, g_xc);
    cudaGetSymbolAddress((void**)&xcT, g_xcT);
    cudaGetSymbolAddress((void**)&dtT, g_dtT);
    cudaGetSymbolAddress((void**)&bcT, g_bcT);
    cudaGetSymbolAddress((void**)&ygT, g_ygT);

    // 1) in_proj: cols<512 -> xmain (raw); cols>=512 -> gT (transposed, silu)
    sgemm<0, 3, false><<<dim3(8, BT / 128), 256>>>(x, DN, in_proj_w, 1024,
                                                   in_proj_b, xmain, INNER, gT, DN);
    // 2) conv: silu, dual store (xc normal + xcT transposed)
    sgemm<1, 2, false><<<dim3(4, BT / 128), 256>>>(xmain, INNER, conv_w, INNER,
                                                   conv_b, xc, INNER, xcT, INNER);
    // 3) bc -> bcT [32][BT]
    bc_kernel<<<BT / 8, 256>>>(xc, bc_w, bc_b, bcT);
    // 4) dt: softplus, transposed-only store -> dtT
    sgemm<2, 1, false><<<dim3(4, BT / 128), 256>>>(xc, INNER, dt_w, INNER,
                                                   dt_b, nullptr, 0, dtT, INNER);
    // 5) selective scan (+gate) -> ygT
    scan_kernel<<<dim3(INNER / 16, BN), 256>>>(xcT, dtT, bcT, A_log, gT, ygT);
    // 6) out_proj: A-transposed GEMM from ygT -> y_out
    sgemm<0, 0, true><<<dim3(2, BT / 128), 256>>>(ygT, BT, out_w, DN,
                                                  out_b, y_out, DN, nullptr, INNER);
    // 7) catastrophe + E8 outputs
    epi_kernel<<<BT / 8, 256>>>(y_out, cat1_w, cat1_b, cat2_w, cat2_b,
                                risk_w, risk_b, e8a_w, e8a_b, e8b_w, e8b_b,
                                cbk, e8_out, idx_out, bif_out);
}

// round 4
// speedup vs baseline: 3.5154x; 1.4028x over previous
#include <cuda_runtime.h>
#include <math.h>
#include <float.h>
#include <stdint.h>

// Problem constants
#define BN    8
#define TN    4096
#define DN    256
#define INNER 512
#define SN    16
#define BT    32768          // B*T
#define NCODE 240

// ---------------- scratch (static device globals; no allocations) ----------
__device__ float g_xmain[(size_t)BT * INNER];  // in_proj cols 0..511
__device__ float g_gT[(size_t)INNER * BT];     // silu(gate), transposed [d][bt]
__device__ float g_xc [(size_t)BT * INNER];    // x_conv (normal)
__device__ float g_xcT[(size_t)INNER * BT];    // x_conv transposed
__device__ float g_dtT[(size_t)INNER * BT];    // dt (softplus), transposed
__device__ float g_bcT[(size_t)32 * BT];       // [B|C] transposed [j][bt]
__device__ float g_ygT[(size_t)INNER * BT];    // scan output (gated), transposed

// ---------------- math helpers --------------------------------------------
__device__ __forceinline__ float fexp(float x) {
    float t = x * 1.4426950408889634f;
    t = fminf(fmaxf(t, -100.f), 100.f);
    float z = t + 12582912.0f;
    int   n = __float_as_int(z) - 0x4B400000;
    float r = t - (z - 12582912.0f);
    float p = 1.5403530394e-4f;
    p = fmaf(p, r, 1.3333558146e-3f);
    p = fmaf(p, r, 9.6181291076e-3f);
    p = fmaf(p, r, 5.5504108664e-2f);
    p = fmaf(p, r, 2.4022650696e-1f);
    p = fmaf(p, r, 6.9314718056e-1f);
    p = fmaf(p, r, 1.0f);
    return __int_as_float(__float_as_int(p) + (n << 23));
}
__device__ __forceinline__ float frcp_fast(float x) {
    float r = __uint_as_float(0x7EF311C3u - __float_as_uint(x));
    r = r * (2.f - x * r);
    r = r * (2.f - x * r);
    r = r * (2.f - x * r);
    return r;
}
__device__ __forceinline__ float fsig(float x)  { return frcp_fast(1.f + fexp(-x)); }
__device__ __forceinline__ float fsilu(float x) { return x * fsig(x); }
__device__ __forceinline__ float sigf(float x)  { return 1.f / (1.f + __expf(-x)); }
__device__ __forceinline__ float softplusf(float x) {
    return x > 20.f ? x : __logf(1.f + fexp(x));
}
__device__ __forceinline__ float geluf(float x) {
    const float c = 0.7978845608028654f;
    float t = tanhf(c * (x + 0.044715f * x * x * x));
    return 0.5f * x * (1.f + t);
}

__device__ __forceinline__ uint32_t f2tf(float f) {
    uint32_t u;
    asm("cvt.rna.tf32.f32 %0, %1;" : "=r"(u) : "f"(f));
    return u;
}

__device__ __forceinline__ void mma_tf32(float c[4], const uint32_t a[4],
                                         const uint32_t b[2]) {
    asm volatile(
        "mma.sync.aligned.m16n8k8.row.col.f32.tf32.tf32.f32 "
        "{%0,%1,%2,%3}, {%4,%5,%6,%7}, {%8,%9}, {%0,%1,%2,%3};\n"
        : "+f"(c[0]), "+f"(c[1]), "+f"(c[2]), "+f"(c[3])
        : "r"(a[0]), "r"(a[1]), "r"(a[2]), "r"(a[3]), "r"(b[0]), "r"(b[1]));
}

// ---------------- TF32 tensor-core GEMM ------------------------------------
// 128x128 block tile, BK=16, 256 threads = 8 warps (2 M x 4 N), warp = 64x32.
// MODE 0: normal store to C (EPI applied)
// MODE 1: transposed store to Ct (EPI applied)  Ct[col][row]
// MODE 2: both (EPI applied)
// MODE 3: in_proj split: bn<512 -> C raw; bn>=512 -> Ct with silu, col-512
// AT: A stored transposed [K][M]
template <int EPI, int MODE, bool AT>
__global__ __launch_bounds__(256)
void tgemm(const float* __restrict__ A, int lda,
           const float* __restrict__ Bm, int ldb,
           const float* __restrict__ bias,
           float* __restrict__ C, int ldc,
           float* __restrict__ Ct, int K)
{
    __shared__ uint32_t As[16][136];
    __shared__ uint32_t Bs[16][136];

    const int tid  = threadIdx.x;
    const int lane = tid & 31;
    const int warp = tid >> 5;
    const int wm   = warp >> 2;         // 0..1  (64 rows)
    const int wn   = warp & 3;          // 0..3  (32 cols)
    const int bm   = blockIdx.y * 128;
    const int bn   = blockIdx.x * 128;
    const int M    = gridDim.y * 128;

    // loader indices
    const int krow = tid >> 4;          // 0..15  (B and AT-A)
    const int kcol = (tid & 15) << 3;   // 0..120
    const int arow = tid >> 1;          // 0..127 (non-AT A)
    const int ak   = (tid & 1) << 3;    // 0 or 8

    const float* Bsrc = Bm + (size_t)krow * ldb + bn + kcol;

    float acc[4][4][4];
#pragma unroll
    for (int i = 0; i < 4; i++)
#pragma unroll
        for (int j = 0; j < 4; j++)
#pragma unroll
            for (int r = 0; r < 4; r++) acc[i][j][r] = 0.f;

    float4 a0, a1, b0, b1;
    if (AT) {
        const float* Asrc = A + (size_t)krow * M + bm + kcol;
        a0 = *(const float4*)(Asrc);
        a1 = *(const float4*)(Asrc + 4);
    } else {
        const float* Asrc = A + (size_t)(bm + arow) * lda + ak;
        a0 = *(const float4*)(Asrc);
        a1 = *(const float4*)(Asrc + 4);
    }
    b0 = *(const float4*)(Bsrc);
    b1 = *(const float4*)(Bsrc + 4);

    const int tig = lane & 3;
    const int gid = lane >> 2;

    for (int kt = 0; kt < K; kt += 16) {
        __syncthreads();
        if (AT) {
            uint4 ua = make_uint4(f2tf(a0.x), f2tf(a0.y), f2tf(a0.z), f2tf(a0.w));
            uint4 ub = make_uint4(f2tf(a1.x), f2tf(a1.y), f2tf(a1.z), f2tf(a1.w));
            *(uint4*)&As[krow][kcol]     = ua;
            *(uint4*)&As[krow][kcol + 4] = ub;
        } else {
            As[ak + 0][arow] = f2tf(a0.x); As[ak + 1][arow] = f2tf(a0.y);
            As[ak + 2][arow] = f2tf(a0.z); As[ak + 3][arow] = f2tf(a0.w);
            As[ak + 4][arow] = f2tf(a1.x); As[ak + 5][arow] = f2tf(a1.y);
            As[ak + 6][arow] = f2tf(a1.z); As[ak + 7][arow] = f2tf(a1.w);
        }
        {
            uint4 ua = make_uint4(f2tf(b0.x), f2tf(b0.y), f2tf(b0.z), f2tf(b0.w));
            uint4 ub = make_uint4(f2tf(b1.x), f2tf(b1.y), f2tf(b1.z), f2tf(b1.w));
            *(uint4*)&Bs[krow][kcol]     = ua;
            *(uint4*)&Bs[krow][kcol + 4] = ub;
        }
        __syncthreads();

        if (kt + 16 < K) {
            if (AT) {
                const float* Asrc = A + (size_t)(kt + 16 + krow) * M + bm + kcol;
                a0 = *(const float4*)(Asrc);
                a1 = *(const float4*)(Asrc + 4);
            } else {
                const float* Asrc = A + (size_t)(bm + arow) * lda + kt + 16 + ak;
                a0 = *(const float4*)(Asrc);
                a1 = *(const float4*)(Asrc + 4);
            }
            b0 = *(const float4*)(Bsrc + (size_t)(kt + 16) * ldb);
            b1 = *(const float4*)(Bsrc + (size_t)(kt + 16) * ldb + 4);
        }

#pragma unroll
        for (int ks = 0; ks < 2; ks++) {
            const int k0 = ks * 8;
            uint32_t af[4][4], bf[4][2];
            const int mbase = wm * 64 + gid;
#pragma unroll
            for (int mf = 0; mf < 4; mf++) {
                af[mf][0] = As[k0 + tig][mbase + mf * 16];
                af[mf][1] = As[k0 + tig][mbase + mf * 16 + 8];
                af[mf][2] = As[k0 + tig + 4][mbase + mf * 16];
                af[mf][3] = As[k0 + tig + 4][mbase + mf * 16 + 8];
            }
            const int nbase = wn * 32 + gid;
#pragma unroll
            for (int nf = 0; nf < 4; nf++) {
                bf[nf][0] = Bs[k0 + tig][nbase + nf * 8];
                bf[nf][1] = Bs[k0 + tig + 4][nbase + nf * 8];
            }
#pragma unroll
            for (int mf = 0; mf < 4; mf++)
#pragma unroll
                for (int nf = 0; nf < 4; nf++)
                    mma_tf32(acc[mf][nf], af[mf], bf[nf]);
        }
    }

    // ---------------- epilogue ----------------
#pragma unroll
    for (int mf = 0; mf < 4; mf++) {
#pragma unroll
        for (int nf = 0; nf < 4; nf++) {
            const int col = wn * 32 + nf * 8 + tig * 2;      // block-local col
            const int row = wm * 64 + mf * 16 + gid;         // block-local row
            float v0 = acc[mf][nf][0] + bias[bn + col];
            float v1 = acc[mf][nf][1] + bias[bn + col + 1];
            float v2 = acc[mf][nf][2] + bias[bn + col];
            float v3 = acc[mf][nf][3] + bias[bn + col + 1];
            if (MODE != 3) {
                if (EPI == 1) { v0 = fsilu(v0); v1 = fsilu(v1); v2 = fsilu(v2); v3 = fsilu(v3); }
                else if (EPI == 2) { v0 = softplusf(v0); v1 = softplusf(v1); v2 = softplusf(v2); v3 = softplusf(v3); }
            }
            if (MODE == 0 || MODE == 2 || (MODE == 3 && bn < 512)) {
                float* p0 = C + (size_t)(bm + row) * ldc + bn + col;
                float* p1 = C + (size_t)(bm + row + 8) * ldc + bn + col;
                *(float2*)p0 = make_float2(v0, v1);
                *(float2*)p1 = make_float2(v2, v3);
            }
            if (MODE == 1 || MODE == 2 || (MODE == 3 && bn >= 512)) {
                float w0 = v0, w1 = v1, w2 = v2, w3 = v3;
                if (MODE == 3) { w0 = fsilu(w0); w1 = fsilu(w1); w2 = fsilu(w2); w3 = fsilu(w3); }
                const int coff = (MODE == 3) ? (bn - 512) : bn;
                float* q0 = Ct + (size_t)(coff + col) * M + bm + row;
                float* q1 = Ct + (size_t)(coff + col + 1) * M + bm + row;
                q0[0] = w0; q1[0] = w1;
                q0[8] = w2; q1[8] = w3;
            }
        }
    }
}

// ---------------- bc projection: [BT,512] @ [512,32] -> bcT [32][BT] ------
__global__ __launch_bounds__(256)
void bc_kernel(const float* __restrict__ xc, const float* __restrict__ w,
               const float* __restrict__ bias, float* __restrict__ bcT)
{
    __shared__ float srow[8][512];
    __shared__ float sbc[8][33];
    const int warp = threadIdx.x >> 5;
    const int lane = threadIdx.x & 31;
    const int r0 = blockIdx.x * 8;
    const int r = r0 + warp;

    const float* xr = xc + (size_t)r * INNER;
    for (int k = lane; k < INNER; k += 32) srow[warp][k] = xr[k];
    __syncwarp();

    float acc = bias[lane];
#pragma unroll 4
    for (int k = 0; k < INNER; k++)
        acc = fmaf(srow[warp][k], w[k * 32 + lane], acc);
    sbc[warp][lane] = acc;
    __syncthreads();

    const int j  = threadIdx.x >> 3;
    const int rr = threadIdx.x & 7;
    bcT[(size_t)j * BT + r0 + rr] = sbc[rr][j];
}

// ---------------- selective scan: one thread per (b,d,s), x4 unroll --------
__global__ __launch_bounds__(256)
void scan_kernel(const float* __restrict__ xcT, const float* __restrict__ dtT,
                 const float* __restrict__ bcT, const float* __restrict__ A_log,
                 const float* __restrict__ gT, float* __restrict__ ygT)
{
    const int lane = threadIdx.x & 31;
    const int warp = threadIdx.x >> 5;
    const int s    = lane & 15;
    const int half = lane >> 4;
    const int b    = blockIdx.y;
    const int d    = blockIdx.x * 16 + warp * 2 + half;

    const float As = -__expf(A_log[d * SN + s]);

    const size_t dbase = (size_t)d * BT + (size_t)b * TN;
    const float4* dt4p = (const float4*)(dtT + dbase);
    const float4* xc4p = (const float4*)(xcT + dbase);
    const float4* g4p  = (const float4*)(gT  + dbase);
    const float4* B4p  = (const float4*)(bcT + (size_t)s * BT + (size_t)b * TN);
    const float4* C4p  = (const float4*)(bcT + (size_t)(16 + s) * BT + (size_t)b * TN);
    float4* y4p        = (float4*)(ygT + dbase);

    float h = 0.f;
    float4 dt4 = dt4p[0], xc4 = xc4p[0], g4 = g4p[0], B4 = B4p[0], C4 = C4p[0];

    const int NG = TN / 4;
    for (int i = 0; i < NG; i++) {
        float4 dtn = dt4, xcn = xc4, gn = g4, Bn = B4, Cn = C4;
        if (i + 1 < NG) {
            dtn = dt4p[i + 1]; xcn = xc4p[i + 1]; gn = g4p[i + 1];
            Bn  = B4p[i + 1];  Cn  = C4p[i + 1];
        }

        float e0 = __expf(dt4.x * As);
        float e1 = __expf(dt4.y * As);
        float e2 = __expf(dt4.z * As);
        float e3 = __expf(dt4.w * As);

        h = fmaf(e0, h, dt4.x * xc4.x * B4.x); float y0 = h * C4.x;
        h = fmaf(e1, h, dt4.y * xc4.y * B4.y); float y1 = h * C4.y;
        h = fmaf(e2, h, dt4.z * xc4.z * B4.z); float y2 = h * C4.z;
        h = fmaf(e3, h, dt4.w * xc4.w * B4.w); float y3 = h * C4.w;

#pragma unroll
        for (int o = 1; o <= 8; o <<= 1) {
            y0 += __shfl_xor_sync(0xffffffffu, y0, o);
            y1 += __shfl_xor_sync(0xffffffffu, y1, o);
            y2 += __shfl_xor_sync(0xffffffffu, y2, o);
            y3 += __shfl_xor_sync(0xffffffffu, y3, o);
        }

        if (s == 0)
            y4p[i] = make_float4(y0 * g4.x, y1 * g4.y, y2 * g4.z, y3 * g4.w);

        dt4 = dtn; xc4 = xcn; g4 = gn; B4 = Bn; C4 = Cn;
    }
}

// ---------------- catastrophe detector + E8 quantizer ----------------------
__global__ __launch_bounds__(256)
void epi_kernel(const float* __restrict__ y,
                const float* __restrict__ cat1_w, const float* __restrict__ cat1_b,
                const float* __restrict__ cat2_w, const float* __restrict__ cat2_b,
                const float* __restrict__ risk_w, const float* __restrict__ risk_b,
                const float* __restrict__ e8a_w,  const float* __restrict__ e8a_b,
                const float* __restrict__ e8b_w,  const float* __restrict__ e8b_b,
                const float* __restrict__ cb,
                float* __restrict__ e8_out, float* __restrict__ idx_out,
                float* __restrict__ bif_out)
{
    __shared__ float sy[8][256];
    __shared__ float sf[8][64];
    __shared__ float se[8][8];

    const int warp = threadIdx.x >> 5;
    const int lane = threadIdx.x & 31;
    const int r = blockIdx.x * 8 + warp;
    const int t = r & (TN - 1);

    const float* yr = y + (size_t)r * DN;
    for (int k = lane; k < DN; k += 32) sy[warp][k] = yr[k];
    __syncwarp();

    float s1 = 0.f, s2 = 0.f;
    if (t > 0) {
        const float* yp1 = yr - DN;
        for (int k = lane; k < DN; k += 32) {
            float dv = sy[warp][k] - yp1[k];
            s1 = fmaf(dv, dv, s1);
        }
        if (t > 1) {
            const float* yp2 = yr - 2 * DN;
            for (int k = lane; k < DN; k += 32) {
                float dv = yp1[k] - yp2[k];
                s2 = fmaf(dv, dv, s2);
            }
        }
    }
#pragma unroll
    for (int o = 16; o; o >>= 1) {
        s1 += __shfl_xor_sync(0xffffffffu, s1, o);
        s2 += __shfl_xor_sync(0xffffffffu, s2, o);
    }
    const float vn   = sqrtf(s1);
    const float vnp  = sqrtf(s2);
    const float accv = fabsf(vn - vnp);

    float f1a = cat1_b[lane], f1b = cat1_b[lane + 32];
    float e1a = e8a_b[lane],  e1b = e8a_b[lane + 32];
#pragma unroll 4
    for (int k = 0; k < DN; k++) {
        const float yv = sy[warp][k];
        f1a = fmaf(yv, cat1_w[k * 64 + lane], f1a);
        f1b = fmaf(yv, cat1_w[k * 64 + lane + 32], f1b);
        e1a = fmaf(yv, e8a_w[k * 64 + lane], e1a);
        e1b = fmaf(yv, e8a_w[k * 64 + lane + 32], e1b);
    }
    f1a = geluf(f1a); f1b = geluf(f1b);
    e1a = geluf(e1a); e1b = geluf(e1b);

    sf[warp][lane] = f1a; sf[warp][lane + 32] = f1b;
    __syncwarp();

    float f2 = cat2_b[lane];
#pragma unroll 8
    for (int k = 0; k < 64; k++)
        f2 = fmaf(sf[warp][k], cat2_w[k * 32 + lane], f2);
    float rp = f2 * risk_w[lane];
#pragma unroll
    for (int o = 16; o; o >>= 1) rp += __shfl_xor_sync(0xffffffffu, rp, o);
    const float risk = sigf(rp + risk_b[0]);

    const float combined = 0.5f * risk + 0.3f * sigf(vn) + 0.2f * sigf(accv);
    if (lane == 0) bif_out[r] = combined > 0.7f ? 1.f : 0.f;

    __syncwarp();
    sf[warp][lane] = e1a; sf[warp][lane + 32] = e1b;
    __syncwarp();
    float e8c = 0.f;
    if (lane < 8) {
        e8c = e8b_b[lane];
#pragma unroll 8
        for (int k = 0; k < 64; k++)
            e8c = fmaf(sf[warp][k], e8b_w[k * 8 + lane], e8c);
        se[warp][lane] = e8c;
    }
    __syncwarp();

    float fn2 = (lane < 8) ? e8c * e8c : 0.f;
#pragma unroll
    for (int o = 16; o; o >>= 1) fn2 += __shfl_xor_sync(0xffffffffu, fn2, o);

    const float f0 = se[warp][0], f1 = se[warp][1], f2v = se[warp][2], f3 = se[warp][3];
    const float f4 = se[warp][4], f5 = se[warp][5], f6v = se[warp][6], f7 = se[warp][7];

    float best = FLT_MAX;
    int bidx = 0x7fffffff;
    for (int c = lane; c < NCODE; c += 32) {
        const float* cp = cb + c * 8;
        float dot = f0 * cp[0] + f1 * cp[1] + f2v * cp[2] + f3 * cp[3]
                  + f4 * cp[4] + f5 * cp[5] + f6v * cp[6] + f7 * cp[7];
        float cn2 = cp[0]*cp[0] + cp[1]*cp[1] + cp[2]*cp[2] + cp[3]*cp[3]
                  + cp[4]*cp[4] + cp[5]*cp[5] + cp[6]*cp[6] + cp[7]*cp[7];
        float d2 = fn2 - 2.f * dot + cn2;
        if (d2 < best) { best = d2; bidx = c; }
    }
#pragma unroll
    for (int o = 16; o; o >>= 1) {
        float ob = __shfl_xor_sync(0xffffffffu, best, o);
        int   oi = __shfl_xor_sync(0xffffffffu, bidx, o);
        if (ob < best || (ob == best && oi < bidx)) { best = ob; bidx = oi; }
    }

    if (lane < 8) {
        const float qv = cb[bidx * 8 + lane];
        const float ec = se[warp][lane];
        e8_out[(size_t)r * 8 + lane] = ec + (qv - ec);
    }
    if (lane == 0) idx_out[r] = (float)bidx;
}

// ---------------- launcher --------------------------------------------------
extern "C" void kernel_launch(void* const* d_in, const int* in_sizes, int n_in,
                              void* d_out, int out_size)
{
    const float* x          = (const float*)d_in[0];
    const float* in_proj_w  = (const float*)d_in[1];
    const float* in_proj_b  = (const float*)d_in[2];
    const float* conv_w     = (const float*)d_in[3];
    const float* conv_b     = (const float*)d_in[4];
    const float* A_log      = (const float*)d_in[5];
    const float* bc_w       = (const float*)d_in[6];
    const float* bc_b       = (const float*)d_in[7];
    const float* dt_w       = (const float*)d_in[8];
    const float* dt_b       = (const float*)d_in[9];
    const float* out_w      = (const float*)d_in[10];
    const float* out_b      = (const float*)d_in[11];
    const float* cat1_w     = (const float*)d_in[12];
    const float* cat1_b     = (const float*)d_in[13];
    const float* cat2_w     = (const float*)d_in[14];
    const float* cat2_b     = (const float*)d_in[15];
    const float* risk_w     = (const float*)d_in[16];
    const float* risk_b     = (const float*)d_in[17];
    const float* e8a_w      = (const float*)d_in[18];
    const float* e8a_b      = (const float*)d_in[19];
    const float* e8b_w      = (const float*)d_in[20];
    const float* e8b_b      = (const float*)d_in[21];
    const float* cbk        = (const float*)d_in[22];

    float* out = (float*)d_out;
    float* y_out   = out;
    float* e8_out  = out + (size_t)BT * DN;
    float* idx_out = out + (size_t)BT * DN + (size_t)BT * 8;
    float* bif_out = idx_out + BT;

    float *xmain, *gT, *xc, *xcT, *dtT, *bcT, *ygT;
    cudaGetSymbolAddress((void**)&xmain, g_xmain);
    cudaGetSymbolAddress((void**)&gT, g_gT);
    cudaGetSymbolAddress((void**)&xc, g_xc);
    cudaGetSymbolAddress((void**)&xcT, g_xcT);
    cudaGetSymbolAddress((void**)&dtT, g_dtT);
    cudaGetSymbolAddress((void**)&bcT, g_bcT);
    cudaGetSymbolAddress((void**)&ygT, g_ygT);

    // 1) in_proj: cols<512 -> xmain (raw); cols>=512 -> gT (transposed, silu)
    tgemm<0, 3, false><<<dim3(8, BT / 128), 256>>>(x, DN, in_proj_w, 1024,
                                                   in_proj_b, xmain, INNER, gT, DN);
    // 2) conv: silu, dual store (xc normal + xcT transposed)
    tgemm<1, 2, false><<<dim3(4, BT / 128), 256>>>(xmain, INNER, conv_w, INNER,
                                                   conv_b, xc, INNER, xcT, INNER);
    // 3) bc -> bcT [32][BT]
    bc_kernel<<<BT / 8, 256>>>(xc, bc_w, bc_b, bcT);
    // 4) dt: softplus, transposed-only store -> dtT
    tgemm<2, 1, false><<<dim3(4, BT / 128), 256>>>(xc, INNER, dt_w, INNER,
                                                   dt_b, nullptr, 0, dtT, INNER);
    // 5) selective scan (+gate) -> ygT
    scan_kernel<<<dim3(INNER / 16, BN), 256>>>(xcT, dtT, bcT, A_log, gT, ygT);
    // 6) out_proj: A-transposed GEMM from ygT -> y_out
    tgemm<0, 0, true><<<dim3(2, BT / 128), 256>>>(ygT, BT, out_w, DN,
                                                  out_b, y_out, DN, nullptr, INNER);
    // 7) catastrophe + E8 outputs
    epi_kernel<<<BT / 8, 256>>>(y_out, cat1_w, cat1_b, cat2_w, cat2_b,
                                risk_w, risk_b, e8a_w, e8a_b, e8b_w, e8b_b,
                                cbk, e8_out, idx_out, bif_out);
}